// round 3
// baseline (speedup 1.0000x reference)
#include <cuda_runtime.h>
#include <cstdint>

typedef unsigned long long u64;

// ---------------------------------------------------------------------------
// f32x2 packed helpers (Blackwell sm_103a)
// ---------------------------------------------------------------------------
__device__ __forceinline__ u64 pack2(float a, float b) {
    u64 r;
    asm("mov.b64 %0, {%1,%2};" : "=l"(r) : "f"(a), "f"(b));
    return r;
}
__device__ __forceinline__ u64 dup2(float a) { return pack2(a, a); }
__device__ __forceinline__ u64 ffma2(u64 a, u64 b, u64 c) {
    u64 d;
    asm("fma.rn.f32x2 %0, %1, %2, %3;" : "=l"(d) : "l"(a), "l"(b), "l"(c));
    return d;
}
__device__ __forceinline__ void unpack2(u64 v, float& lo, float& hi) {
    asm("mov.b64 {%0,%1}, %2;" : "=f"(lo), "=f"(hi) : "l"(v));
}

// ---------------------------------------------------------------------------
// Coefficient table: C[combo(t0,t1,t2)][t3][output i], combo = t0*9+t1*3+t2
// linear index = combo*12 + t3*4 + i   (324 floats)
// ---------------------------------------------------------------------------
__device__ float g_coef[324];

// ---------------------------------------------------------------------------
// Setup kernel: build 16x16 circuit unitary (each of 16 threads owns one
// column in registers -> zero syncs during gate application), then derive
// the 324 multilinear coefficients.
// ---------------------------------------------------------------------------
__device__ __forceinline__ float2 cmulf(float2 a, float2 b) {
    return make_float2(a.x * b.x - a.y * b.y, a.x * b.y + a.y * b.x);
}
__device__ __forceinline__ float2 caddf(float2 a, float2 b) {
    return make_float2(a.x + b.x, a.y + b.y);
}

template <int WIRE>
__device__ __forceinline__ void apply1q(float2 (&u)[16], float2 a00, float2 a01,
                                        float2 a10, float2 a11) {
    constexpr int m = 1 << (3 - WIRE);
#pragma unroll
    for (int k = 0; k < 16; k++) {
        if (!(k & m)) {
            float2 lo = u[k], hi = u[k | m];
            u[k]     = caddf(cmulf(a00, lo), cmulf(a01, hi));
            u[k | m] = caddf(cmulf(a10, lo), cmulf(a11, hi));
        }
    }
}

template <int WIRE>
__device__ __forceinline__ void applyU3(float2 (&u)[16], const float* w) {
    float th = w[0], ph = w[1], lm = w[2];
    float ct = cosf(0.5f * th), st = sinf(0.5f * th);
    float cph = cosf(ph), sph = sinf(ph);
    float cl = cosf(lm), sl = sinf(lm);
    float cpl = cph * cl - sph * sl;
    float spl = sph * cl + cph * sl;
    float2 a00 = make_float2(ct, 0.f);
    float2 a01 = make_float2(-cl * st, -sl * st);
    float2 a10 = make_float2(cph * st, sph * st);
    float2 a11 = make_float2(cpl * ct, spl * ct);
    apply1q<WIRE>(u, a00, a01, a10, a11);
}

template <int WIRE>
__device__ __forceinline__ void applyRY(float2 (&u)[16], float t) {
    float c = cosf(0.5f * t), s = sinf(0.5f * t);
    apply1q<WIRE>(u, make_float2(c, 0.f), make_float2(-s, 0.f),
                  make_float2(s, 0.f), make_float2(c, 0.f));
}

template <int WIRE>
__device__ __forceinline__ void applyRZ(float2 (&u)[16], float t) {
    float c = cosf(0.5f * t), s = sinf(0.5f * t);
    float2 em = make_float2(c, -s);  // e^{-it/2}
    float2 ep = make_float2(c, s);   // e^{+it/2}
    constexpr int m = 1 << (3 - WIRE);
#pragma unroll
    for (int k = 0; k < 16; k++) u[k] = cmulf((k & m) ? ep : em, u[k]);
}

template <int CW, int TW>
__device__ __forceinline__ void applyCNOT(float2 (&u)[16]) {
    constexpr int cm = 1 << (3 - CW), tm = 1 << (3 - TW);
#pragma unroll
    for (int k = 0; k < 16; k++) {
        if ((k & cm) && !(k & tm)) {
            float2 t = u[k];
            u[k] = u[k | tm];
            u[k | tm] = t;
        }
    }
}

template <int WA, int WB>
__device__ __forceinline__ void su4(float2 (&u)[16], const float* const* W, int base) {
    applyU3<WA>(u, W[base + 0]);
    applyU3<WB>(u, W[base + 1]);
    applyCNOT<WA, WB>(u);
    applyRY<WA>(u, W[base + 2][0]);
    applyRZ<WB>(u, W[base + 3][0]);
    applyCNOT<WB, WA>(u);
    applyRY<WA>(u, W[base + 4][0]);
    applyCNOT<WA, WB>(u);
    applyU3<WA>(u, W[base + 5]);
    applyU3<WB>(u, W[base + 6]);
}

__global__ void build_coef_kernel(
    const float* w0, const float* w1, const float* w2, const float* w3,
    const float* w4, const float* w5, const float* w6, const float* w7,
    const float* w8, const float* w9, const float* w10, const float* w11,
    const float* w12, const float* w13) {
    __shared__ float2 Ush[16][16];  // Ush[row][col]
    const float* W[14] = {w0, w1, w2, w3, w4, w5, w6, w7, w8, w9, w10, w11, w12, w13};

    int tid = threadIdx.x;

    // Phase 1: 16 threads, each evolves one column of U in registers.
    if (tid < 16) {
        int c = tid;
        float2 u[16];
#pragma unroll
        for (int k = 0; k < 16; k++) u[k] = make_float2(k == c ? 1.f : 0.f, 0.f);

        // layer 0 (weights 0..6)
        su4<0, 1>(u, W, 0);
        su4<1, 2>(u, W, 0);
        su4<2, 3>(u, W, 0);
        su4<3, 0>(u, W, 0);
        // layer 1 (weights 7..13)
        su4<0, 1>(u, W, 7);
        su4<1, 2>(u, W, 7);
        su4<2, 3>(u, W, 7);
        su4<3, 0>(u, W, 7);

#pragma unroll
        for (int k = 0; k < 16; k++) Ush[k][c] = u[k];
    }
    __syncthreads();

    // Phase 2: 324 threads compute coefficients.
    // out_i = v^T M_i v,  M_i[r][c] = Re sum_k conj(U[k][r]) s_i(k) U[k][c]
    // C = (1/16) Tr(M_i * (B_t0 x B_t1 x B_t2 x B_t3)),  B = {I, Z, X}
    if (tid < 324) {
        int i = tid & 3;
        int t3 = (tid >> 2) % 3;
        int combo = tid / 12;
        int t2 = combo % 3, t1 = (combo / 3) % 3, t0 = combo / 9;
        int t[4] = {t0, t1, t2, t3};
        int mask = 0;
#pragma unroll
        for (int w = 0; w < 4; w++)
            if (t[w] == 2) mask |= 1 << (3 - w);
        float acc = 0.f;
        for (int r = 0; r < 16; r++) {
            int c = r ^ mask;
            float sgn = 1.f;
#pragma unroll
            for (int w = 0; w < 4; w++)
                if (t[w] == 1 && ((r >> (3 - w)) & 1)) sgn = -sgn;
            float m = 0.f;
#pragma unroll
            for (int k = 0; k < 16; k++) {
                float si = ((k >> (3 - i)) & 1) ? -1.f : 1.f;
                float2 a = Ush[k][r], b = Ush[k][c];
                m += si * (a.x * b.x + a.y * b.y);
            }
            acc += sgn * m;
        }
        g_coef[tid] = acc * 0.0625f;
    }
}

// ---------------------------------------------------------------------------
// Main kernel: 1 patch per thread.
//   a_w = pi * sigmoid(x_w); weights per wire = (1, cos a, sin a)
//   sigmoid via __expf + rcp (exact enough); let u = sigma - 0.5:
//     sin a = cos(pi*u)  (even poly deg 8),  cos a = -sin(pi*u) (odd poly deg 9)
//   Contraction vectorized as f32x2 over output pairs (0,1) and (2,3).
// ---------------------------------------------------------------------------
__global__ void __launch_bounds__(256) quanv_main(const float4* __restrict__ patches,
                                                  float4* __restrict__ out, int B) {
    __shared__ ulonglong2 shc[81];  // [combo*3 + t3] -> float4 of 4 outputs
    {
        float* shf = reinterpret_cast<float*>(shc);
        for (int j = threadIdx.x; j < 324; j += 256) shf[j] = g_coef[j];
    }
    __syncthreads();

    int b = blockIdx.x * 256 + threadIdx.x;
    if (b >= B) return;

    float4 xv = patches[b];
    float xs[4] = {xv.x, xv.y, xv.z, xv.w};

    u64 cd[4], sd[4];  // duplicated (cos a_w, cos a_w), (sin a_w, sin a_w)
#pragma unroll
    for (int w = 0; w < 4; w++) {
        float x = xs[w];
        float e = __expf(-x);
        float sg = __fdividef(1.0f, 1.0f + e);
        float uu = sg - 0.5f;  // in (-0.5, 0.5)
        float z = uu * uu;
        // sin(pi*u), Taylor deg 9 (|err| < 4e-6 on [-0.5,0.5])
        float sp = uu * (3.14159265358979f +
                   z * (-5.16771278004997f +
                   z * (2.55016403987735f +
                   z * (-0.599264529320792f + z * 0.0821458866111282f))));
        // cos(pi*u), Taylor deg 8 (|err| < 3e-5)
        float cp = 1.0f + z * (-4.93480220054468f +
                         z * (4.05871212641677f +
                         z * (-1.33526276885459f + z * 0.235330630358514f)));
        cd[w] = dup2(-sp);  // cos a
        sd[w] = dup2(cp);   // sin a
    }

    u64 o01, o23, a1_01, a1_23, a2_01, a2_23;
#pragma unroll
    for (int t0 = 0; t0 < 3; t0++) {
#pragma unroll
        for (int t1 = 0; t1 < 3; t1++) {
#pragma unroll
            for (int t2 = 0; t2 < 3; t2++) {
                int combo = t0 * 9 + t1 * 3 + t2;
                ulonglong2 k0 = shc[combo * 3 + 0];
                ulonglong2 k1 = shc[combo * 3 + 1];
                ulonglong2 k2 = shc[combo * 3 + 2];
                u64 e01 = ffma2(cd[3], k1.x, k0.x);
                e01 = ffma2(sd[3], k2.x, e01);
                u64 e23 = ffma2(cd[3], k1.y, k0.y);
                e23 = ffma2(sd[3], k2.y, e23);
                if (t2 == 0) { a2_01 = e01; a2_23 = e23; }
                else {
                    u64 w = (t2 == 1) ? cd[2] : sd[2];
                    a2_01 = ffma2(w, e01, a2_01);
                    a2_23 = ffma2(w, e23, a2_23);
                }
            }
            if (t1 == 0) { a1_01 = a2_01; a1_23 = a2_23; }
            else {
                u64 w = (t1 == 1) ? cd[1] : sd[1];
                a1_01 = ffma2(w, a2_01, a1_01);
                a1_23 = ffma2(w, a2_23, a1_23);
            }
        }
        if (t0 == 0) { o01 = a1_01; o23 = a1_23; }
        else {
            u64 w = (t0 == 1) ? cd[0] : sd[0];
            o01 = ffma2(w, a1_01, o01);
            o23 = ffma2(w, a1_23, o23);
        }
    }

    float f0, f1, f2, f3;
    unpack2(o01, f0, f1);
    unpack2(o23, f2, f3);
    out[b] = make_float4(f0, f1, f2, f3);
}

// ---------------------------------------------------------------------------
extern "C" void kernel_launch(void* const* d_in, const int* in_sizes, int n_in,
                              void* d_out, int out_size) {
    const float* patches = (const float*)d_in[0];
    int B = in_sizes[0] / 4;

    build_coef_kernel<<<1, 384>>>(
        (const float*)d_in[1], (const float*)d_in[2], (const float*)d_in[3],
        (const float*)d_in[4], (const float*)d_in[5], (const float*)d_in[6],
        (const float*)d_in[7], (const float*)d_in[8], (const float*)d_in[9],
        (const float*)d_in[10], (const float*)d_in[11], (const float*)d_in[12],
        (const float*)d_in[13], (const float*)d_in[14]);

    int blocks = (B + 255) / 256;
    quanv_main<<<blocks, 256>>>((const float4*)patches, (float4*)d_out, B);
}

// round 4
// speedup vs baseline: 2.7927x; 2.7927x over previous
#include <cuda_runtime.h>
#include <cstdint>

typedef unsigned long long u64;

// ---------------------------------------------------------------------------
// f32x2 packed helpers (Blackwell sm_103a)
// ---------------------------------------------------------------------------
__device__ __forceinline__ u64 pack2(float a, float b) {
    u64 r;
    asm("mov.b64 %0, {%1,%2};" : "=l"(r) : "f"(a), "f"(b));
    return r;
}
__device__ __forceinline__ u64 dup2(float a) { return pack2(a, a); }
__device__ __forceinline__ u64 ffma2(u64 a, u64 b, u64 c) {
    u64 d;
    asm("fma.rn.f32x2 %0, %1, %2, %3;" : "=l"(d) : "l"(a), "l"(b), "l"(c));
    return d;
}
__device__ __forceinline__ void unpack2(u64 v, float& lo, float& hi) {
    asm("mov.b64 {%0,%1}, %2;" : "=f"(lo), "=f"(hi) : "l"(v));
}

// ---------------------------------------------------------------------------
// Coefficient table: index (p*9+q)*4 + i, p = t0*3+t1, q = t2*3+t3,
// i = output wire.  t in {0:I, 1:Z(->cos a), 2:X(->sin a)} per wire.
// ---------------------------------------------------------------------------
__device__ float g_coef[324];

__device__ __forceinline__ float2 cmulf(float2 a, float2 b) {
    return make_float2(a.x * b.x - a.y * b.y, a.x * b.y + a.y * b.x);
}
__device__ __forceinline__ float2 caddf(float2 a, float2 b) {
    return make_float2(a.x + b.x, a.y + b.y);
}

// ---------------------------------------------------------------------------
// Setup kernel (1 block, 384 threads), fully parallelized:
//  S1: 14 threads build the 14 distinct 2x2 gate matrices (2 layers x 7 gates;
//      the 4 pairs within a layer reuse the same weights).
//  S2: 8 threads compose two 4x4 SU4 matrices by column evolution.
//  S3: 256 threads apply 8 two-qubit embeddings to the 16x16 unitary
//      (double-buffered shared, 1 sync per gate).
//  S4: 324 threads compute the multilinear coefficients.
// ---------------------------------------------------------------------------
__global__ void build_coef_kernel(
    const float* w0, const float* w1, const float* w2, const float* w3,
    const float* w4, const float* w5, const float* w6, const float* w7,
    const float* w8, const float* w9, const float* w10, const float* w11,
    const float* w12, const float* w13) {
    __shared__ float2 gm[14][4];      // 2x2 gate matrices [g00,g01,g10,g11]
    __shared__ float2 su4m[2][16];    // two 4x4 SU4 matrices, row-major
    __shared__ float2 Ubuf[2][16][16];  // [buf][row k][col c]
    const float* W[14] = {w0, w1, w2, w3, w4, w5, w6, w7, w8, w9, w10, w11, w12, w13};

    int tid = threadIdx.x;

    // ---- Stage 1: gate matrices -----------------------------------------
    if (tid < 14) {
        int j = tid % 7;  // gate slot within layer; layer = tid / 7
        const float* w = W[tid];
        float2 m00, m01, m10, m11;
        if (j == 0 || j == 1 || j == 5 || j == 6) {  // U3
            float th = w[0], ph = w[1], lm = w[2];
            float st, ct, sph, cph, sl, cl;
            sincosf(0.5f * th, &st, &ct);
            sincosf(ph, &sph, &cph);
            sincosf(lm, &sl, &cl);
            m00 = make_float2(ct, 0.f);
            m01 = make_float2(-cl * st, -sl * st);
            m10 = make_float2(cph * st, sph * st);
            float cpl = cph * cl - sph * sl;
            float spl = sph * cl + cph * sl;
            m11 = make_float2(cpl * ct, spl * ct);
        } else if (j == 2 || j == 4) {  // RY
            float s, c;
            sincosf(0.5f * w[0], &s, &c);
            m00 = make_float2(c, 0.f); m01 = make_float2(-s, 0.f);
            m10 = make_float2(s, 0.f); m11 = make_float2(c, 0.f);
        } else {  // RZ
            float s, c;
            sincosf(0.5f * w[0], &s, &c);
            m00 = make_float2(c, -s); m01 = make_float2(0.f, 0.f);
            m10 = make_float2(0.f, 0.f); m11 = make_float2(c, s);
        }
        gm[tid][0] = m00; gm[tid][1] = m01; gm[tid][2] = m10; gm[tid][3] = m11;
    }
    __syncthreads();

    // ---- Stage 2: two 4x4 SU4 matrices (a = high bit, b = low bit) ------
    if (tid < 8) {
        int L = tid >> 2, c = tid & 3;
        float2 v[4];
#pragma unroll
        for (int i = 0; i < 4; i++) v[i] = make_float2(i == c ? 1.f : 0.f, 0.f);

        auto ap = [&](int gi, int m) {
            float2 g00 = gm[L * 7 + gi][0], g01 = gm[L * 7 + gi][1];
            float2 g10 = gm[L * 7 + gi][2], g11 = gm[L * 7 + gi][3];
#pragma unroll
            for (int idx = 0; idx < 4; idx++) {
                if (!(idx & m)) {
                    float2 lo = v[idx], hi = v[idx | m];
                    v[idx]     = caddf(cmulf(g00, lo), cmulf(g01, hi));
                    v[idx | m] = caddf(cmulf(g10, lo), cmulf(g11, hi));
                }
            }
        };
        auto swp = [&](int i, int j) { float2 t = v[i]; v[i] = v[j]; v[j] = t; };

        ap(0, 2);        // U3 on a
        ap(1, 1);        // U3 on b
        swp(2, 3);       // CNOT a->b
        ap(2, 2);        // RY on a
        ap(3, 1);        // RZ on b
        swp(1, 3);       // CNOT b->a
        ap(4, 2);        // RY on a
        swp(2, 3);       // CNOT a->b
        ap(5, 2);        // U3 on a
        ap(6, 1);        // U3 on b
#pragma unroll
        for (int r = 0; r < 4; r++) su4m[L][r * 4 + c] = v[r];
    }

    // ---- Stage 3: build 16x16 unitary -----------------------------------
    if (tid < 256) {
        int k = tid >> 4, c = tid & 15;
        Ubuf[0][k][c] = make_float2(k == c ? 1.f : 0.f, 0.f);
    }

    const int gL[8]  = {0, 0, 0, 0, 1, 1, 1, 1};
    const int gwa[8] = {0, 1, 2, 3, 0, 1, 2, 3};
    const int gwb[8] = {1, 2, 3, 0, 1, 2, 3, 0};
    int cur = 0;
#pragma unroll
    for (int g = 0; g < 8; g++) {
        __syncthreads();
        if (tid < 256) {
            int k = tid >> 4, c = tid & 15;
            int ma = 1 << (3 - gwa[g]);
            int mb = 1 << (3 - gwb[g]);
            int i2 = ((k & ma) ? 2 : 0) | ((k & mb) ? 1 : 0);
            int base = k & ~(ma | mb);
            int L = gL[g];
            float2 acc = make_float2(0.f, 0.f);
#pragma unroll
            for (int j = 0; j < 4; j++) {
                int row = base | ((j & 2) ? ma : 0) | ((j & 1) ? mb : 0);
                acc = caddf(acc, cmulf(su4m[L][i2 * 4 + j], Ubuf[cur][row][c]));
            }
            Ubuf[cur ^ 1][k][c] = acc;
        }
        cur ^= 1;
    }
    __syncthreads();

    // ---- Stage 4: coefficients ------------------------------------------
    // out_i = sum_{t} C[t] prod_w w_w[t_w];  C = (1/16) Tr(M_i (B_t0 x..x B_t3))
    if (tid < 324) {
        int i = tid & 3;
        int pq = tid >> 2;       // 0..80
        int q = pq % 9, p = pq / 9;
        int t[4] = {p / 3, p % 3, q / 3, q % 3};
        int mask = 0;
#pragma unroll
        for (int w = 0; w < 4; w++)
            if (t[w] == 2) mask |= 1 << (3 - w);
        float acc = 0.f;
        for (int r = 0; r < 16; r++) {
            int c = r ^ mask;
            float sgn = 1.f;
#pragma unroll
            for (int w = 0; w < 4; w++)
                if (t[w] == 1 && ((r >> (3 - w)) & 1)) sgn = -sgn;
            float m = 0.f;
#pragma unroll
            for (int k = 0; k < 16; k++) {
                float si = ((k >> (3 - i)) & 1) ? -1.f : 1.f;
                float2 a = Ubuf[cur][k][r], b = Ubuf[cur][k][c];
                m += si * (a.x * b.x + a.y * b.y);
            }
            acc += sgn * m;
        }
        g_coef[(p * 9 + q) * 4 + i] = acc * 0.0625f;
    }
}

// ---------------------------------------------------------------------------
// Main kernel: 1 patch per thread; rank-factored contraction:
//   out = sum_p pw[p] * ( C[p][0] + sum_{q=1..8} qw[q]*C[p][q] )
// with pw = w0 (x) w1, qw = w2 (x) w3 pair-products (w = (1, cos a, sin a)).
// 160 FFMA2 + 81 LDS.128 per patch.
// ---------------------------------------------------------------------------
__global__ void __launch_bounds__(256) quanv_main(const float4* __restrict__ patches,
                                                  float4* __restrict__ out, int B) {
    __shared__ ulonglong2 shc[81];  // [p*9+q] -> float4 of 4 outputs
    {
        float* shf = reinterpret_cast<float*>(shc);
        for (int j = threadIdx.x; j < 324; j += 256) shf[j] = g_coef[j];
    }
    __syncthreads();

    int b = blockIdx.x * 256 + threadIdx.x;
    if (b >= B) return;

    float4 xv = patches[b];
    float xs[4] = {xv.x, xv.y, xv.z, xv.w};

    float cw[4], sw[4];
#pragma unroll
    for (int w = 0; w < 4; w++) {
        float x = xs[w];
        float e = __expf(-x);
        float sg = __fdividef(1.0f, 1.0f + e);
        float uu = sg - 0.5f;  // in (-0.5, 0.5)
        float z = uu * uu;
        // sin(pi*u) deg-9, cos(pi*u) deg-8 (abs err < 3e-5 on [-0.5,0.5])
        float sp = uu * (3.14159265358979f +
                   z * (-5.16771278004997f +
                   z * (2.55016403987735f +
                   z * (-0.599264529320792f + z * 0.0821458866111282f))));
        float cp = 1.0f + z * (-4.93480220054468f +
                         z * (4.05871212641677f +
                         z * (-1.33526276885459f + z * 0.235330630358514f)));
        cw[w] = -sp;  // cos a
        sw[w] = cp;   // sin a
    }

    // pair products (index 0 is the constant 1 -> handled structurally)
    u64 qwd[9];
    qwd[1] = dup2(cw[3]);
    qwd[2] = dup2(sw[3]);
    qwd[3] = dup2(cw[2]);
    qwd[4] = dup2(cw[2] * cw[3]);
    qwd[5] = dup2(cw[2] * sw[3]);
    qwd[6] = dup2(sw[2]);
    qwd[7] = dup2(sw[2] * cw[3]);
    qwd[8] = dup2(sw[2] * sw[3]);

    float pws[9];
    pws[1] = cw[1];
    pws[2] = sw[1];
    pws[3] = cw[0];
    pws[4] = cw[0] * cw[1];
    pws[5] = cw[0] * sw[1];
    pws[6] = sw[0];
    pws[7] = sw[0] * cw[1];
    pws[8] = sw[0] * sw[1];

    u64 acc01, acc23;
#pragma unroll
    for (int p = 0; p < 9; p++) {
        const ulonglong2* base = &shc[p * 9];
        ulonglong2 k0 = base[0];
        u64 s01 = k0.x, s23 = k0.y;
#pragma unroll
        for (int q = 1; q < 9; q++) {
            ulonglong2 kq = base[q];
            s01 = ffma2(qwd[q], kq.x, s01);
            s23 = ffma2(qwd[q], kq.y, s23);
        }
        if (p == 0) {
            acc01 = s01;
            acc23 = s23;
        } else {
            u64 pw = dup2(pws[p]);
            acc01 = ffma2(pw, s01, acc01);
            acc23 = ffma2(pw, s23, acc23);
        }
    }

    float f0, f1, f2, f3;
    unpack2(acc01, f0, f1);
    unpack2(acc23, f2, f3);
    out[b] = make_float4(f0, f1, f2, f3);
}

// ---------------------------------------------------------------------------
extern "C" void kernel_launch(void* const* d_in, const int* in_sizes, int n_in,
                              void* d_out, int out_size) {
    const float* patches = (const float*)d_in[0];
    int B = in_sizes[0] / 4;

    build_coef_kernel<<<1, 384>>>(
        (const float*)d_in[1], (const float*)d_in[2], (const float*)d_in[3],
        (const float*)d_in[4], (const float*)d_in[5], (const float*)d_in[6],
        (const float*)d_in[7], (const float*)d_in[8], (const float*)d_in[9],
        (const float*)d_in[10], (const float*)d_in[11], (const float*)d_in[12],
        (const float*)d_in[13], (const float*)d_in[14]);

    int blocks = (B + 255) / 256;
    quanv_main<<<blocks, 256>>>((const float4*)patches, (float4*)d_out, B);
}

// round 5
// speedup vs baseline: 3.4300x; 1.2282x over previous
#include <cuda_runtime.h>
#include <cstdint>

typedef unsigned long long u64;

// ---------------------------------------------------------------------------
// f32x2 packed helpers (Blackwell sm_103a)
// ---------------------------------------------------------------------------
__device__ __forceinline__ u64 pack2(float a, float b) {
    u64 r;
    asm("mov.b64 %0, {%1,%2};" : "=l"(r) : "f"(a), "f"(b));
    return r;
}
__device__ __forceinline__ u64 dup2(float a) { return pack2(a, a); }
__device__ __forceinline__ u64 ffma2(u64 a, u64 b, u64 c) {
    u64 d;
    asm("fma.rn.f32x2 %0, %1, %2, %3;" : "=l"(d) : "l"(a), "l"(b), "l"(c));
    return d;
}
__device__ __forceinline__ void unpack2(u64 v, float& lo, float& hi) {
    asm("mov.b64 {%0,%1}, %2;" : "=f"(lo), "=f"(hi) : "l"(v));
}

// ---------------------------------------------------------------------------
// Coefficient table: index (p*9+q)*4 + i, p = t0*3+t1, q = t2*3+t3,
// i = output wire.  t in {0:I, 1:Z(->cos a), 2:X(->sin a)} per wire.
// ---------------------------------------------------------------------------
__device__ __align__(16) float g_coef[324];

__device__ __forceinline__ float2 cmulf(float2 a, float2 b) {
    return make_float2(a.x * b.x - a.y * b.y, a.x * b.y + a.y * b.x);
}
__device__ __forceinline__ float2 caddf(float2 a, float2 b) {
    return make_float2(a.x + b.x, a.y + b.y);
}

// ---------------------------------------------------------------------------
// Setup kernel (1 block, 384 threads), fully parallel, MUFU trig.
// ---------------------------------------------------------------------------
__global__ void build_coef_kernel(
    const float* w0, const float* w1, const float* w2, const float* w3,
    const float* w4, const float* w5, const float* w6, const float* w7,
    const float* w8, const float* w9, const float* w10, const float* w11,
    const float* w12, const float* w13) {
    __shared__ float2 gm[14][4];        // 2x2 gate matrices
    __shared__ float2 su4m[2][16];      // two 4x4 SU4 matrices, row-major
    __shared__ float2 Ubuf[2][16][16];  // [buf][row k][col c]
    const float* W[14] = {w0, w1, w2, w3, w4, w5, w6, w7, w8, w9, w10, w11, w12, w13};

    int tid = threadIdx.x;

    // ---- Stage 1: gate matrices (fast trig; weights are O(1) normals) ----
    if (tid < 14) {
        int j = tid % 7;
        const float* w = W[tid];
        float2 m00, m01, m10, m11;
        if (j == 0 || j == 1 || j == 5 || j == 6) {  // U3
            float th = w[0], ph = w[1], lm = w[2];
            float st, ct, sph, cph, sl, cl;
            __sincosf(0.5f * th, &st, &ct);
            __sincosf(ph, &sph, &cph);
            __sincosf(lm, &sl, &cl);
            m00 = make_float2(ct, 0.f);
            m01 = make_float2(-cl * st, -sl * st);
            m10 = make_float2(cph * st, sph * st);
            float cpl = cph * cl - sph * sl;
            float spl = sph * cl + cph * sl;
            m11 = make_float2(cpl * ct, spl * ct);
        } else if (j == 2 || j == 4) {  // RY
            float s, c;
            __sincosf(0.5f * w[0], &s, &c);
            m00 = make_float2(c, 0.f); m01 = make_float2(-s, 0.f);
            m10 = make_float2(s, 0.f); m11 = make_float2(c, 0.f);
        } else {  // RZ
            float s, c;
            __sincosf(0.5f * w[0], &s, &c);
            m00 = make_float2(c, -s); m01 = make_float2(0.f, 0.f);
            m10 = make_float2(0.f, 0.f); m11 = make_float2(c, s);
        }
        gm[tid][0] = m00; gm[tid][1] = m01; gm[tid][2] = m10; gm[tid][3] = m11;
    }
    __syncthreads();

    // ---- Stage 2: two 4x4 SU4 matrices (a = high bit, b = low bit) ------
    if (tid < 8) {
        int L = tid >> 2, c = tid & 3;
        float2 v[4];
#pragma unroll
        for (int i = 0; i < 4; i++) v[i] = make_float2(i == c ? 1.f : 0.f, 0.f);

        auto ap = [&](int gi, int m) {
            float2 g00 = gm[L * 7 + gi][0], g01 = gm[L * 7 + gi][1];
            float2 g10 = gm[L * 7 + gi][2], g11 = gm[L * 7 + gi][3];
#pragma unroll
            for (int idx = 0; idx < 4; idx++) {
                if (!(idx & m)) {
                    float2 lo = v[idx], hi = v[idx | m];
                    v[idx]     = caddf(cmulf(g00, lo), cmulf(g01, hi));
                    v[idx | m] = caddf(cmulf(g10, lo), cmulf(g11, hi));
                }
            }
        };
        auto swp = [&](int i, int j) { float2 t = v[i]; v[i] = v[j]; v[j] = t; };

        ap(0, 2);   // U3 a
        ap(1, 1);   // U3 b
        swp(2, 3);  // CNOT a->b
        ap(2, 2);   // RY a
        ap(3, 1);   // RZ b
        swp(1, 3);  // CNOT b->a
        ap(4, 2);   // RY a
        swp(2, 3);  // CNOT a->b
        ap(5, 2);   // U3 a
        ap(6, 1);   // U3 b
#pragma unroll
        for (int r = 0; r < 4; r++) su4m[L][r * 4 + c] = v[r];
    }

    // ---- Stage 3: build 16x16 unitary -----------------------------------
    if (tid < 256) {
        int k = tid >> 4, c = tid & 15;
        Ubuf[0][k][c] = make_float2(k == c ? 1.f : 0.f, 0.f);
    }

    const int gL[8]  = {0, 0, 0, 0, 1, 1, 1, 1};
    const int gwa[8] = {0, 1, 2, 3, 0, 1, 2, 3};
    const int gwb[8] = {1, 2, 3, 0, 1, 2, 3, 0};
    int cur = 0;
#pragma unroll
    for (int g = 0; g < 8; g++) {
        __syncthreads();
        if (tid < 256) {
            int k = tid >> 4, c = tid & 15;
            int ma = 1 << (3 - gwa[g]);
            int mb = 1 << (3 - gwb[g]);
            int i2 = ((k & ma) ? 2 : 0) | ((k & mb) ? 1 : 0);
            int base = k & ~(ma | mb);
            int L = gL[g];
            float2 acc = make_float2(0.f, 0.f);
#pragma unroll
            for (int j = 0; j < 4; j++) {
                int row = base | ((j & 2) ? ma : 0) | ((j & 1) ? mb : 0);
                acc = caddf(acc, cmulf(su4m[L][i2 * 4 + j], Ubuf[cur][row][c]));
            }
            Ubuf[cur ^ 1][k][c] = acc;
        }
        cur ^= 1;
    }
    __syncthreads();

    // ---- Stage 4: coefficients ------------------------------------------
    if (tid < 324) {
        int i = tid & 3;
        int pq = tid >> 2;  // 0..80
        int q = pq % 9, p = pq / 9;
        int t[4] = {p / 3, p % 3, q / 3, q % 3};
        int mask = 0;
#pragma unroll
        for (int w = 0; w < 4; w++)
            if (t[w] == 2) mask |= 1 << (3 - w);
        float acc = 0.f;
        for (int r = 0; r < 16; r++) {
            int c = r ^ mask;
            float sgn = 1.f;
#pragma unroll
            for (int w = 0; w < 4; w++)
                if (t[w] == 1 && ((r >> (3 - w)) & 1)) sgn = -sgn;
            float m = 0.f;
#pragma unroll
            for (int k = 0; k < 16; k++) {
                float si = ((k >> (3 - i)) & 1) ? -1.f : 1.f;
                float2 a = Ubuf[cur][k][r], b = Ubuf[cur][k][c];
                m += si * (a.x * b.x + a.y * b.y);
            }
            acc += sgn * m;
        }
        g_coef[(p * 9 + q) * 4 + i] = acc * 0.0625f;
    }
}

// ---------------------------------------------------------------------------
// Main kernel: 2 patches per thread (A and B) so each coefficient LDS.128
// broadcast feeds 4 ffma2 instead of 2 (L1 crossbar was the R3 bottleneck).
// Per patch: ~40.5 LDS.128, ~178 ffma2.
// ---------------------------------------------------------------------------
struct PatchW {
    u64 qwd[9];   // duplicated (w2 x w3) pair products, index 1..8 used
    float pws[9]; // (w0 x w1) pair products, index 1..8 used
};

__device__ __forceinline__ void make_weights(float4 xv, PatchW& P) {
    float xs[4] = {xv.x, xv.y, xv.z, xv.w};
    float cw[4], sw[4];
#pragma unroll
    for (int w = 0; w < 4; w++) {
        float x = xs[w];
        float e = __expf(-x);
        float sg = __fdividef(1.0f, 1.0f + e);
        float uu = sg - 0.5f;  // in (-0.5, 0.5)
        float z = uu * uu;
        // sin(pi*u) deg-9, cos(pi*u) deg-8 (abs err < 3e-5 on [-0.5,0.5])
        float sp = uu * (3.14159265358979f +
                   z * (-5.16771278004997f +
                   z * (2.55016403987735f +
                   z * (-0.599264529320792f + z * 0.0821458866111282f))));
        float cp = 1.0f + z * (-4.93480220054468f +
                         z * (4.05871212641677f +
                         z * (-1.33526276885459f + z * 0.235330630358514f)));
        cw[w] = -sp;  // cos a
        sw[w] = cp;   // sin a
    }
    P.qwd[1] = dup2(cw[3]);
    P.qwd[2] = dup2(sw[3]);
    P.qwd[3] = dup2(cw[2]);
    P.qwd[4] = dup2(cw[2] * cw[3]);
    P.qwd[5] = dup2(cw[2] * sw[3]);
    P.qwd[6] = dup2(sw[2]);
    P.qwd[7] = dup2(sw[2] * cw[3]);
    P.qwd[8] = dup2(sw[2] * sw[3]);
    P.pws[1] = cw[1];
    P.pws[2] = sw[1];
    P.pws[3] = cw[0];
    P.pws[4] = cw[0] * cw[1];
    P.pws[5] = cw[0] * sw[1];
    P.pws[6] = sw[0];
    P.pws[7] = sw[0] * cw[1];
    P.pws[8] = sw[0] * sw[1];
}

__global__ void __launch_bounds__(128) quanv_main(const float4* __restrict__ patches,
                                                  float4* __restrict__ out, int B) {
    __shared__ ulonglong2 shc[81];  // [p*9+q] -> float4 of coeffs for 4 outputs
    if (threadIdx.x < 81) {
        shc[threadIdx.x] = reinterpret_cast<const ulonglong2*>(g_coef)[threadIdx.x];
    }
    __syncthreads();

    int ta = blockIdx.x * 256 + threadIdx.x;  // patch A
    int tb = ta + 128;                        // patch B
    bool va = ta < B, vb = tb < B;

    PatchW A, Bw;
    if (va) make_weights(patches[ta], A);
    if (vb) make_weights(patches[tb], Bw);

    u64 aA01, aA23, aB01, aB23;
#pragma unroll
    for (int p = 0; p < 9; p++) {
        const ulonglong2* base = &shc[p * 9];
        ulonglong2 k0 = base[0];
        u64 sA01 = k0.x, sA23 = k0.y;
        u64 sB01 = k0.x, sB23 = k0.y;
#pragma unroll
        for (int q = 1; q < 9; q++) {
            ulonglong2 kq = base[q];
            sA01 = ffma2(A.qwd[q], kq.x, sA01);
            sA23 = ffma2(A.qwd[q], kq.y, sA23);
            sB01 = ffma2(Bw.qwd[q], kq.x, sB01);
            sB23 = ffma2(Bw.qwd[q], kq.y, sB23);
        }
        if (p == 0) {
            aA01 = sA01; aA23 = sA23;
            aB01 = sB01; aB23 = sB23;
        } else {
            u64 pa = dup2(A.pws[p]);
            u64 pb = dup2(Bw.pws[p]);
            aA01 = ffma2(pa, sA01, aA01);
            aA23 = ffma2(pa, sA23, aA23);
            aB01 = ffma2(pb, sB01, aB01);
            aB23 = ffma2(pb, sB23, aB23);
        }
    }

    float f0, f1, f2, f3;
    if (va) {
        unpack2(aA01, f0, f1);
        unpack2(aA23, f2, f3);
        out[ta] = make_float4(f0, f1, f2, f3);
    }
    if (vb) {
        unpack2(aB01, f0, f1);
        unpack2(aB23, f2, f3);
        out[tb] = make_float4(f0, f1, f2, f3);
    }
}

// ---------------------------------------------------------------------------
extern "C" void kernel_launch(void* const* d_in, const int* in_sizes, int n_in,
                              void* d_out, int out_size) {
    const float* patches = (const float*)d_in[0];
    int B = in_sizes[0] / 4;

    build_coef_kernel<<<1, 384>>>(
        (const float*)d_in[1], (const float*)d_in[2], (const float*)d_in[3],
        (const float*)d_in[4], (const float*)d_in[5], (const float*)d_in[6],
        (const float*)d_in[7], (const float*)d_in[8], (const float*)d_in[9],
        (const float*)d_in[10], (const float*)d_in[11], (const float*)d_in[12],
        (const float*)d_in[13], (const float*)d_in[14]);

    int blocks = (B + 255) / 256;
    quanv_main<<<blocks, 128>>>((const float4*)patches, (float4*)d_out, B);
}

// round 7
// speedup vs baseline: 3.8794x; 1.1310x over previous
#include <cuda_runtime.h>
#include <cstdint>

typedef unsigned long long u64;

// ---------------------------------------------------------------------------
// f32x2 packed helpers (Blackwell sm_103a)
// ---------------------------------------------------------------------------
__device__ __forceinline__ u64 pack2(float a, float b) {
    u64 r;
    asm("mov.b64 %0, {%1,%2};" : "=l"(r) : "f"(a), "f"(b));
    return r;
}
__device__ __forceinline__ u64 dup2(float a) { return pack2(a, a); }
__device__ __forceinline__ u64 ffma2(u64 a, u64 b, u64 c) {
    u64 d;
    asm("fma.rn.f32x2 %0, %1, %2, %3;" : "=l"(d) : "l"(a), "l"(b), "l"(c));
    return d;
}
__device__ __forceinline__ u64 fmul2(u64 a, u64 b) {
    u64 d;
    asm("mul.rn.f32x2 %0, %1, %2;" : "=l"(d) : "l"(a), "l"(b));
    return d;
}
__device__ __forceinline__ void unpack2(u64 v, float& lo, float& hi) {
    asm("mov.b64 {%0,%1}, %2;" : "=f"(lo), "=f"(hi) : "l"(v));
}

// ---------------------------------------------------------------------------
// Coefficient table: index (p*9+q)*4 + i, p = t0*3+t1, q = t2*3+t3,
// i = output wire.  t in {0:I, 1:Z(->cos a), 2:X(->sin a)} per wire.
// ---------------------------------------------------------------------------
__device__ __align__(16) float g_coef[324];

__device__ __forceinline__ float2 cmulf(float2 a, float2 b) {
    return make_float2(a.x * b.x - a.y * b.y, a.x * b.y + a.y * b.x);
}
__device__ __forceinline__ float2 caddf(float2 a, float2 b) {
    return make_float2(a.x + b.x, a.y + b.y);
}

// ---------------------------------------------------------------------------
// Setup kernel (1 block, 384 threads), fully parallel.
// ---------------------------------------------------------------------------
__global__ void build_coef_kernel(
    const float* w0, const float* w1, const float* w2, const float* w3,
    const float* w4, const float* w5, const float* w6, const float* w7,
    const float* w8, const float* w9, const float* w10, const float* w11,
    const float* w12, const float* w13) {
    __shared__ float2 gm[14][4];        // 2x2 gate matrices
    __shared__ float2 su4m[2][16];      // two 4x4 SU4 matrices, row-major
    __shared__ float2 Ubuf[2][16][16];  // [buf][row k][col c]
    __shared__ float2 Ut[16][18];       // transposed: Ut[c][k]; pad 18 so each
                                        // row (144 B) stays 16B-aligned for LDS.128
    __shared__ float Gsh[4][16][16];    // G[i][r][c]
    const float* W[14] = {w0, w1, w2, w3, w4, w5, w6, w7, w8, w9, w10, w11, w12, w13};

    int tid = threadIdx.x;

    // ---- Stage 1: gate matrices ------------------------------------------
    if (tid < 14) {
        int j = tid % 7;
        const float* w = W[tid];
        float2 m00, m01, m10, m11;
        if (j == 0 || j == 1 || j == 5 || j == 6) {  // U3
            float th = w[0], ph = w[1], lm = w[2];
            float st, ct, sph, cph, sl, cl;
            __sincosf(0.5f * th, &st, &ct);
            __sincosf(ph, &sph, &cph);
            __sincosf(lm, &sl, &cl);
            m00 = make_float2(ct, 0.f);
            m01 = make_float2(-cl * st, -sl * st);
            m10 = make_float2(cph * st, sph * st);
            float cpl = cph * cl - sph * sl;
            float spl = sph * cl + cph * sl;
            m11 = make_float2(cpl * ct, spl * ct);
        } else if (j == 2 || j == 4) {  // RY
            float s, c;
            __sincosf(0.5f * w[0], &s, &c);
            m00 = make_float2(c, 0.f); m01 = make_float2(-s, 0.f);
            m10 = make_float2(s, 0.f); m11 = make_float2(c, 0.f);
        } else {  // RZ
            float s, c;
            __sincosf(0.5f * w[0], &s, &c);
            m00 = make_float2(c, -s); m01 = make_float2(0.f, 0.f);
            m10 = make_float2(0.f, 0.f); m11 = make_float2(c, s);
        }
        gm[tid][0] = m00; gm[tid][1] = m01; gm[tid][2] = m10; gm[tid][3] = m11;
    }
    __syncthreads();

    // ---- Stage 2: two 4x4 SU4 matrices (a = high bit, b = low bit) -------
    if (tid < 8) {
        int L = tid >> 2, c = tid & 3;
        float2 v[4];
#pragma unroll
        for (int i = 0; i < 4; i++) v[i] = make_float2(i == c ? 1.f : 0.f, 0.f);

        auto ap = [&](int gi, int m) {
            float2 g00 = gm[L * 7 + gi][0], g01 = gm[L * 7 + gi][1];
            float2 g10 = gm[L * 7 + gi][2], g11 = gm[L * 7 + gi][3];
#pragma unroll
            for (int idx = 0; idx < 4; idx++) {
                if (!(idx & m)) {
                    float2 lo = v[idx], hi = v[idx | m];
                    v[idx]     = caddf(cmulf(g00, lo), cmulf(g01, hi));
                    v[idx | m] = caddf(cmulf(g10, lo), cmulf(g11, hi));
                }
            }
        };
        auto swp = [&](int i, int j) { float2 t = v[i]; v[i] = v[j]; v[j] = t; };

        ap(0, 2);   // U3 a
        ap(1, 1);   // U3 b
        swp(2, 3);  // CNOT a->b
        ap(2, 2);   // RY a
        ap(3, 1);   // RZ b
        swp(1, 3);  // CNOT b->a
        ap(4, 2);   // RY a
        swp(2, 3);  // CNOT a->b
        ap(5, 2);   // U3 a
        ap(6, 1);   // U3 b
#pragma unroll
        for (int r = 0; r < 4; r++) su4m[L][r * 4 + c] = v[r];
    }

    // ---- Stage 3: build 16x16 unitary -----------------------------------
    if (tid < 256) {
        int k = tid >> 4, c = tid & 15;
        Ubuf[0][k][c] = make_float2(k == c ? 1.f : 0.f, 0.f);
    }

    const int gL[8]  = {0, 0, 0, 0, 1, 1, 1, 1};
    const int gwa[8] = {0, 1, 2, 3, 0, 1, 2, 3};
    const int gwb[8] = {1, 2, 3, 0, 1, 2, 3, 0};
    int cur = 0;
#pragma unroll
    for (int g = 0; g < 8; g++) {
        __syncthreads();
        if (tid < 256) {
            int k = tid >> 4, c = tid & 15;
            int ma = 1 << (3 - gwa[g]);
            int mb = 1 << (3 - gwb[g]);
            int i2 = ((k & ma) ? 2 : 0) | ((k & mb) ? 1 : 0);
            int base = k & ~(ma | mb);
            int L = gL[g];
            float2 acc = make_float2(0.f, 0.f);
#pragma unroll
            for (int j = 0; j < 4; j++) {
                int row = base | ((j & 2) ? ma : 0) | ((j & 1) ? mb : 0);
                acc = caddf(acc, cmulf(su4m[L][i2 * 4 + j], Ubuf[cur][row][c]));
            }
            Ubuf[cur ^ 1][k][c] = acc;
        }
        cur ^= 1;
    }
    __syncthreads();

    // ---- Stage 3.5: transpose so column access is contiguous over k -----
    if (tid < 256) {
        int k = tid >> 4, c = tid & 15;
        Ut[c][k] = Ubuf[cur][k][c];
    }
    __syncthreads();

    // ---- Stage 4a: G[i][r][c] = sum_k s_i(k) Re(conj U[k][r] U[k][c]) ---
    if (tid < 256) {
        int r = tid >> 4, c = tid & 15;
        float g[4] = {0.f, 0.f, 0.f, 0.f};
        const float4* pr = reinterpret_cast<const float4*>(&Ut[r][0]);
        const float4* pc = reinterpret_cast<const float4*>(&Ut[c][0]);
#pragma unroll
        for (int j = 0; j < 8; j++) {
            float4 ar = pr[j], ac = pc[j];
            float d0 = ar.x * ac.x + ar.y * ac.y;  // k = 2j
            float d1 = ar.z * ac.z + ar.w * ac.w;  // k = 2j+1
            int k0 = 2 * j, k1 = 2 * j + 1;
#pragma unroll
            for (int i = 0; i < 4; i++) {
                float s0 = ((k0 >> (3 - i)) & 1) ? -d0 : d0;
                float s1 = ((k1 >> (3 - i)) & 1) ? -d1 : d1;
                g[i] += s0 + s1;
            }
        }
#pragma unroll
        for (int i = 0; i < 4; i++) Gsh[i][r][c] = g[i];
    }
    __syncthreads();

    // ---- Stage 4b: coefficients -----------------------------------------
    if (tid < 324) {
        int i = tid & 3;
        int pq = tid >> 2;  // 0..80
        int q = pq % 9, p = pq / 9;
        int t[4] = {p / 3, p % 3, q / 3, q % 3};
        int mask = 0, zmask = 0;
#pragma unroll
        for (int w = 0; w < 4; w++) {
            if (t[w] == 2) mask |= 1 << (3 - w);
            if (t[w] == 1) zmask |= 1 << (3 - w);
        }
        float acc = 0.f;
#pragma unroll
        for (int r = 0; r < 16; r++) {
            float sgn = (__popc(r & zmask) & 1) ? -1.f : 1.f;
            acc += sgn * Gsh[i][r][r ^ mask];
        }
        g_coef[(p * 9 + q) * 4 + i] = acc * 0.0625f;
    }
}

// ---------------------------------------------------------------------------
// Main kernel: 3 patches per thread; each coefficient LDS.128 broadcast
// feeds 6 ffma2.  Trig polynomials vectorized in f32x2 across wire pairs.
// ---------------------------------------------------------------------------
struct PatchW {
    u64 qwd[9];    // duplicated (w2 x w3) pair products, index 1..8 used
    float pws[9];  // (w0 x w1) pair products, index 1..8 used
};

__device__ __forceinline__ void make_weights(float4 xv, PatchW& P) {
    float xs[4] = {xv.x, xv.y, xv.z, xv.w};
    float us[4];
#pragma unroll
    for (int w = 0; w < 4; w++) {
        float e = __expf(-xs[w]);
        us[w] = __fdividef(1.0f, 1.0f + e) - 0.5f;  // u in (-0.5, 0.5)
    }
    // packed polynomials: lanes = (wire0,wire1) and (wire2,wire3)
    u64 u01 = pack2(us[0], us[1]);
    u64 u23 = pack2(us[2], us[3]);
    float cw[4], sw[4];
#pragma unroll
    for (int h = 0; h < 2; h++) {
        u64 uu = h ? u23 : u01;
        u64 z = fmul2(uu, uu);
        // sin(pi*u) deg-9 / cos(pi*u) deg-8 (abs err < 3e-5 on [-0.5,0.5])
        u64 sp = ffma2(z, dup2(0.0821458866111282f), dup2(-0.599264529320792f));
        sp = ffma2(z, sp, dup2(2.55016403987735f));
        sp = ffma2(z, sp, dup2(-5.16771278004997f));
        sp = ffma2(z, sp, dup2(3.14159265358979f));
        sp = fmul2(sp, uu);
        u64 cp = ffma2(z, dup2(0.235330630358514f), dup2(-1.33526276885459f));
        cp = ffma2(z, cp, dup2(4.05871212641677f));
        cp = ffma2(z, cp, dup2(-4.93480220054468f));
        cp = ffma2(z, cp, dup2(1.0f));
        float a, b;
        unpack2(sp, a, b);
        cw[2 * h] = -a; cw[2 * h + 1] = -b;  // cos a = -sin(pi*u)
        unpack2(cp, a, b);
        sw[2 * h] = a; sw[2 * h + 1] = b;    // sin a =  cos(pi*u)
    }
    P.qwd[1] = dup2(cw[3]);
    P.qwd[2] = dup2(sw[3]);
    P.qwd[3] = dup2(cw[2]);
    P.qwd[4] = dup2(cw[2] * cw[3]);
    P.qwd[5] = dup2(cw[2] * sw[3]);
    P.qwd[6] = dup2(sw[2]);
    P.qwd[7] = dup2(sw[2] * cw[3]);
    P.qwd[8] = dup2(sw[2] * sw[3]);
    P.pws[1] = cw[1];
    P.pws[2] = sw[1];
    P.pws[3] = cw[0];
    P.pws[4] = cw[0] * cw[1];
    P.pws[5] = cw[0] * sw[1];
    P.pws[6] = sw[0];
    P.pws[7] = sw[0] * cw[1];
    P.pws[8] = sw[0] * sw[1];
}

__global__ void __launch_bounds__(128) quanv_main(const float4* __restrict__ patches,
                                                  float4* __restrict__ out, int B) {
    __shared__ ulonglong2 shc[81];  // [p*9+q] -> float4 of coeffs for 4 outputs
    if (threadIdx.x < 81) {
        shc[threadIdx.x] = reinterpret_cast<const ulonglong2*>(g_coef)[threadIdx.x];
    }
    __syncthreads();

    int ta = blockIdx.x * 384 + threadIdx.x;  // patch A
    int tb = ta + 128;                        // patch B
    int tc = ta + 256;                        // patch C
    bool va = ta < B, vb = tb < B, vc = tc < B;

    PatchW A, Bw, Cw;
    if (va) make_weights(patches[ta], A);
    if (vb) make_weights(patches[tb], Bw);
    if (vc) make_weights(patches[tc], Cw);

    u64 aA01, aA23, aB01, aB23, aC01, aC23;
#pragma unroll
    for (int p = 0; p < 9; p++) {
        const ulonglong2* base = &shc[p * 9];
        ulonglong2 k0 = base[0];
        u64 sA01 = k0.x, sA23 = k0.y;
        u64 sB01 = k0.x, sB23 = k0.y;
        u64 sC01 = k0.x, sC23 = k0.y;
#pragma unroll
        for (int q = 1; q < 9; q++) {
            ulonglong2 kq = base[q];
            sA01 = ffma2(A.qwd[q], kq.x, sA01);
            sA23 = ffma2(A.qwd[q], kq.y, sA23);
            sB01 = ffma2(Bw.qwd[q], kq.x, sB01);
            sB23 = ffma2(Bw.qwd[q], kq.y, sB23);
            sC01 = ffma2(Cw.qwd[q], kq.x, sC01);
            sC23 = ffma2(Cw.qwd[q], kq.y, sC23);
        }
        if (p == 0) {
            aA01 = sA01; aA23 = sA23;
            aB01 = sB01; aB23 = sB23;
            aC01 = sC01; aC23 = sC23;
        } else {
            u64 pa = dup2(A.pws[p]);
            u64 pb = dup2(Bw.pws[p]);
            u64 pc = dup2(Cw.pws[p]);
            aA01 = ffma2(pa, sA01, aA01);
            aA23 = ffma2(pa, sA23, aA23);
            aB01 = ffma2(pb, sB01, aB01);
            aB23 = ffma2(pb, sB23, aB23);
            aC01 = ffma2(pc, sC01, aC01);
            aC23 = ffma2(pc, sC23, aC23);
        }
    }

    float f0, f1, f2, f3;
    if (va) {
        unpack2(aA01, f0, f1);
        unpack2(aA23, f2, f3);
        out[ta] = make_float4(f0, f1, f2, f3);
    }
    if (vb) {
        unpack2(aB01, f0, f1);
        unpack2(aB23, f2, f3);
        out[tb] = make_float4(f0, f1, f2, f3);
    }
    if (vc) {
        unpack2(aC01, f0, f1);
        unpack2(aC23, f2, f3);
        out[tc] = make_float4(f0, f1, f2, f3);
    }
}

// ---------------------------------------------------------------------------
extern "C" void kernel_launch(void* const* d_in, const int* in_sizes, int n_in,
                              void* d_out, int out_size) {
    const float* patches = (const float*)d_in[0];
    int B = in_sizes[0] / 4;

    build_coef_kernel<<<1, 384>>>(
        (const float*)d_in[1], (const float*)d_in[2], (const float*)d_in[3],
        (const float*)d_in[4], (const float*)d_in[5], (const float*)d_in[6],
        (const float*)d_in[7], (const float*)d_in[8], (const float*)d_in[9],
        (const float*)d_in[10], (const float*)d_in[11], (const float*)d_in[12],
        (const float*)d_in[13], (const float*)d_in[14]);

    int blocks = (B + 383) / 384;
    quanv_main<<<blocks, 128>>>((const float4*)patches, (float4*)d_out, B);
}

// round 8
// speedup vs baseline: 4.1142x; 1.0605x over previous
#include <cuda_runtime.h>
#include <cstdint>

typedef unsigned long long u64;

// ---------------------------------------------------------------------------
// f32x2 packed helpers (Blackwell sm_103a)
// ---------------------------------------------------------------------------
__device__ __forceinline__ u64 pack2(float a, float b) {
    u64 r;
    asm("mov.b64 %0, {%1,%2};" : "=l"(r) : "f"(a), "f"(b));
    return r;
}
__device__ __forceinline__ u64 dup2(float a) { return pack2(a, a); }
__device__ __forceinline__ u64 ffma2(u64 a, u64 b, u64 c) {
    u64 d;
    asm("fma.rn.f32x2 %0, %1, %2, %3;" : "=l"(d) : "l"(a), "l"(b), "l"(c));
    return d;
}
__device__ __forceinline__ u64 fmul2(u64 a, u64 b) {
    u64 d;
    asm("mul.rn.f32x2 %0, %1, %2;" : "=l"(d) : "l"(a), "l"(b));
    return d;
}
__device__ __forceinline__ void unpack2(u64 v, float& lo, float& hi) {
    asm("mov.b64 {%0,%1}, %2;" : "=f"(lo), "=f"(hi) : "l"(v));
}

// ---------------------------------------------------------------------------
// Coefficient table: index (p*9+q)*4 + i, p = t0*3+t1, q = t2*3+t3,
// i = output wire.  t in {0:I, 1:Z(->cos a), 2:X(->sin a)} per wire.
// ---------------------------------------------------------------------------
__device__ __align__(16) float g_coef[324];

__device__ __forceinline__ float2 cmulf(float2 a, float2 b) {
    return make_float2(a.x * b.x - a.y * b.y, a.x * b.y + a.y * b.x);
}
__device__ __forceinline__ float2 caddf(float2 a, float2 b) {
    return make_float2(a.x + b.x, a.y + b.y);
}

// ---------------------------------------------------------------------------
// Setup kernel (1 block, 384 threads), fully parallel.  Triggers PDL launch
// of the main kernel immediately so main's prelude overlaps this kernel.
// ---------------------------------------------------------------------------
__global__ void build_coef_kernel(
    const float* w0, const float* w1, const float* w2, const float* w3,
    const float* w4, const float* w5, const float* w6, const float* w7,
    const float* w8, const float* w9, const float* w10, const float* w11,
    const float* w12, const float* w13) {
    cudaTriggerProgrammaticLaunchCompletion();

    __shared__ float2 gm[14][4];        // 2x2 gate matrices
    __shared__ float2 su4m[2][16];      // two 4x4 SU4 matrices, row-major
    __shared__ float2 Ubuf[2][16][16];  // [buf][row k][col c]
    __shared__ float2 Ut[16][18];       // transposed Ut[c][k]; 144B rows keep
                                        // 16B alignment for LDS.128
    __shared__ float Gsh[4][16][16];    // G[i][r][c]
    const float* W[14] = {w0, w1, w2, w3, w4, w5, w6, w7, w8, w9, w10, w11, w12, w13};

    int tid = threadIdx.x;

    // ---- Stage 1: gate matrices ------------------------------------------
    if (tid < 14) {
        int j = tid % 7;
        const float* w = W[tid];
        float2 m00, m01, m10, m11;
        if (j == 0 || j == 1 || j == 5 || j == 6) {  // U3
            float th = w[0], ph = w[1], lm = w[2];
            float st, ct, sph, cph, sl, cl;
            __sincosf(0.5f * th, &st, &ct);
            __sincosf(ph, &sph, &cph);
            __sincosf(lm, &sl, &cl);
            m00 = make_float2(ct, 0.f);
            m01 = make_float2(-cl * st, -sl * st);
            m10 = make_float2(cph * st, sph * st);
            float cpl = cph * cl - sph * sl;
            float spl = sph * cl + cph * sl;
            m11 = make_float2(cpl * ct, spl * ct);
        } else if (j == 2 || j == 4) {  // RY
            float s, c;
            __sincosf(0.5f * w[0], &s, &c);
            m00 = make_float2(c, 0.f); m01 = make_float2(-s, 0.f);
            m10 = make_float2(s, 0.f); m11 = make_float2(c, 0.f);
        } else {  // RZ
            float s, c;
            __sincosf(0.5f * w[0], &s, &c);
            m00 = make_float2(c, -s); m01 = make_float2(0.f, 0.f);
            m10 = make_float2(0.f, 0.f); m11 = make_float2(c, s);
        }
        gm[tid][0] = m00; gm[tid][1] = m01; gm[tid][2] = m10; gm[tid][3] = m11;
    }
    __syncthreads();

    // ---- Stage 2: two 4x4 SU4 matrices (a = high bit, b = low bit) -------
    if (tid < 8) {
        int L = tid >> 2, c = tid & 3;
        float2 v[4];
#pragma unroll
        for (int i = 0; i < 4; i++) v[i] = make_float2(i == c ? 1.f : 0.f, 0.f);

        auto ap = [&](int gi, int m) {
            float2 g00 = gm[L * 7 + gi][0], g01 = gm[L * 7 + gi][1];
            float2 g10 = gm[L * 7 + gi][2], g11 = gm[L * 7 + gi][3];
#pragma unroll
            for (int idx = 0; idx < 4; idx++) {
                if (!(idx & m)) {
                    float2 lo = v[idx], hi = v[idx | m];
                    v[idx]     = caddf(cmulf(g00, lo), cmulf(g01, hi));
                    v[idx | m] = caddf(cmulf(g10, lo), cmulf(g11, hi));
                }
            }
        };
        auto swp = [&](int i, int j) { float2 t = v[i]; v[i] = v[j]; v[j] = t; };

        ap(0, 2);   // U3 a
        ap(1, 1);   // U3 b
        swp(2, 3);  // CNOT a->b
        ap(2, 2);   // RY a
        ap(3, 1);   // RZ b
        swp(1, 3);  // CNOT b->a
        ap(4, 2);   // RY a
        swp(2, 3);  // CNOT a->b
        ap(5, 2);   // U3 a
        ap(6, 1);   // U3 b
#pragma unroll
        for (int r = 0; r < 4; r++) su4m[L][r * 4 + c] = v[r];
    }

    // ---- Stage 3: build 16x16 unitary -----------------------------------
    if (tid < 256) {
        int k = tid >> 4, c = tid & 15;
        Ubuf[0][k][c] = make_float2(k == c ? 1.f : 0.f, 0.f);
    }

    const int gL[8]  = {0, 0, 0, 0, 1, 1, 1, 1};
    const int gwa[8] = {0, 1, 2, 3, 0, 1, 2, 3};
    const int gwb[8] = {1, 2, 3, 0, 1, 2, 3, 0};
    int cur = 0;
#pragma unroll
    for (int g = 0; g < 8; g++) {
        __syncthreads();
        if (tid < 256) {
            int k = tid >> 4, c = tid & 15;
            int ma = 1 << (3 - gwa[g]);
            int mb = 1 << (3 - gwb[g]);
            int i2 = ((k & ma) ? 2 : 0) | ((k & mb) ? 1 : 0);
            int base = k & ~(ma | mb);
            int L = gL[g];
            float2 acc = make_float2(0.f, 0.f);
#pragma unroll
            for (int j = 0; j < 4; j++) {
                int row = base | ((j & 2) ? ma : 0) | ((j & 1) ? mb : 0);
                acc = caddf(acc, cmulf(su4m[L][i2 * 4 + j], Ubuf[cur][row][c]));
            }
            Ubuf[cur ^ 1][k][c] = acc;
        }
        cur ^= 1;
    }
    __syncthreads();

    // ---- Stage 3.5: transpose so column access is contiguous over k -----
    if (tid < 256) {
        int k = tid >> 4, c = tid & 15;
        Ut[c][k] = Ubuf[cur][k][c];
    }
    __syncthreads();

    // ---- Stage 4a: G[i][r][c] = sum_k s_i(k) Re(conj U[k][r] U[k][c]) ---
    if (tid < 256) {
        int r = tid >> 4, c = tid & 15;
        float g[4] = {0.f, 0.f, 0.f, 0.f};
        const float4* pr = reinterpret_cast<const float4*>(&Ut[r][0]);
        const float4* pc = reinterpret_cast<const float4*>(&Ut[c][0]);
#pragma unroll
        for (int j = 0; j < 8; j++) {
            float4 ar = pr[j], ac = pc[j];
            float d0 = ar.x * ac.x + ar.y * ac.y;  // k = 2j
            float d1 = ar.z * ac.z + ar.w * ac.w;  // k = 2j+1
            int k0 = 2 * j, k1 = 2 * j + 1;
#pragma unroll
            for (int i = 0; i < 4; i++) {
                float s0 = ((k0 >> (3 - i)) & 1) ? -d0 : d0;
                float s1 = ((k1 >> (3 - i)) & 1) ? -d1 : d1;
                g[i] += s0 + s1;
            }
        }
#pragma unroll
        for (int i = 0; i < 4; i++) Gsh[i][r][c] = g[i];
    }
    __syncthreads();

    // ---- Stage 4b: coefficients -----------------------------------------
    if (tid < 324) {
        int i = tid & 3;
        int pq = tid >> 2;  // 0..80
        int q = pq % 9, p = pq / 9;
        int t[4] = {p / 3, p % 3, q / 3, q % 3};
        int mask = 0, zmask = 0;
#pragma unroll
        for (int w = 0; w < 4; w++) {
            if (t[w] == 2) mask |= 1 << (3 - w);
            if (t[w] == 1) zmask |= 1 << (3 - w);
        }
        float acc = 0.f;
#pragma unroll
        for (int r = 0; r < 16; r++) {
            float sgn = (__popc(r & zmask) & 1) ? -1.f : 1.f;
            acc += sgn * Gsh[i][r][r ^ mask];
        }
        g_coef[(p * 9 + q) * 4 + i] = acc * 0.0625f;
    }
}

// ---------------------------------------------------------------------------
// Main kernel: 2 patches per thread, 256 threads/block, forced 64 regs for
// 50% occupancy (the ffma2 floor is ~10.3us; everything else is latency).
// Coefficient-independent prelude (loads + trig) runs BEFORE the PDL grid
// dependency sync, overlapping the setup kernel.
// ---------------------------------------------------------------------------
struct PatchW {
    u64 qwd[9];    // duplicated (w2 x w3) pair products, index 1..8 used
    float pws[9];  // (w0 x w1) pair products, index 1..8 used
};

__device__ __forceinline__ void make_weights(float4 xv, PatchW& P) {
    float xs[4] = {xv.x, xv.y, xv.z, xv.w};
    float us[4];
#pragma unroll
    for (int w = 0; w < 4; w++) {
        float e = __expf(-xs[w]);
        us[w] = __fdividef(1.0f, 1.0f + e) - 0.5f;  // u in (-0.5, 0.5)
    }
    // packed polynomials: lanes = (wire0,wire1) and (wire2,wire3)
    u64 u01 = pack2(us[0], us[1]);
    u64 u23 = pack2(us[2], us[3]);
    float cw[4], sw[4];
#pragma unroll
    for (int h = 0; h < 2; h++) {
        u64 uu = h ? u23 : u01;
        u64 z = fmul2(uu, uu);
        // sin(pi*u) deg-9 / cos(pi*u) deg-8 (abs err < 3e-5 on [-0.5,0.5])
        u64 sp = ffma2(z, dup2(0.0821458866111282f), dup2(-0.599264529320792f));
        sp = ffma2(z, sp, dup2(2.55016403987735f));
        sp = ffma2(z, sp, dup2(-5.16771278004997f));
        sp = ffma2(z, sp, dup2(3.14159265358979f));
        sp = fmul2(sp, uu);
        u64 cp = ffma2(z, dup2(0.235330630358514f), dup2(-1.33526276885459f));
        cp = ffma2(z, cp, dup2(4.05871212641677f));
        cp = ffma2(z, cp, dup2(-4.93480220054468f));
        cp = ffma2(z, cp, dup2(1.0f));
        float a, b;
        unpack2(sp, a, b);
        cw[2 * h] = -a; cw[2 * h + 1] = -b;  // cos a = -sin(pi*u)
        unpack2(cp, a, b);
        sw[2 * h] = a; sw[2 * h + 1] = b;    // sin a =  cos(pi*u)
    }
    P.qwd[1] = dup2(cw[3]);
    P.qwd[2] = dup2(sw[3]);
    P.qwd[3] = dup2(cw[2]);
    P.qwd[4] = dup2(cw[2] * cw[3]);
    P.qwd[5] = dup2(cw[2] * sw[3]);
    P.qwd[6] = dup2(sw[2]);
    P.qwd[7] = dup2(sw[2] * cw[3]);
    P.qwd[8] = dup2(sw[2] * sw[3]);
    P.pws[1] = cw[1];
    P.pws[2] = sw[1];
    P.pws[3] = cw[0];
    P.pws[4] = cw[0] * cw[1];
    P.pws[5] = cw[0] * sw[1];
    P.pws[6] = sw[0];
    P.pws[7] = sw[0] * cw[1];
    P.pws[8] = sw[0] * sw[1];
}

__global__ void __launch_bounds__(256, 4) quanv_main(const float4* __restrict__ patches,
                                                     float4* __restrict__ out, int B) {
    __shared__ ulonglong2 shc[81];  // [p*9+q] -> float4 of coeffs for 4 outputs

    int ta = blockIdx.x * 512 + threadIdx.x;  // patch A
    int tb = ta + 256;                        // patch B
    bool va = ta < B, vb = tb < B;

    // ---- prelude: independent of coefficients (overlaps setup kernel) ----
    PatchW A, Bw;
    if (va) make_weights(patches[ta], A);
    if (vb) make_weights(patches[tb], Bw);

    // ---- wait for setup kernel's g_coef writes ---------------------------
    cudaGridDependencySynchronize();
    if (threadIdx.x < 81) {
        shc[threadIdx.x] = reinterpret_cast<const ulonglong2*>(g_coef)[threadIdx.x];
    }
    __syncthreads();

    u64 aA01, aA23, aB01, aB23;
#pragma unroll
    for (int p = 0; p < 9; p++) {
        const ulonglong2* base = &shc[p * 9];
        ulonglong2 k0 = base[0];
        u64 sA01 = k0.x, sA23 = k0.y;
        u64 sB01 = k0.x, sB23 = k0.y;
#pragma unroll
        for (int q = 1; q < 9; q++) {
            ulonglong2 kq = base[q];
            sA01 = ffma2(A.qwd[q], kq.x, sA01);
            sA23 = ffma2(A.qwd[q], kq.y, sA23);
            sB01 = ffma2(Bw.qwd[q], kq.x, sB01);
            sB23 = ffma2(Bw.qwd[q], kq.y, sB23);
        }
        if (p == 0) {
            aA01 = sA01; aA23 = sA23;
            aB01 = sB01; aB23 = sB23;
        } else {
            u64 pa = dup2(A.pws[p]);
            u64 pb = dup2(Bw.pws[p]);
            aA01 = ffma2(pa, sA01, aA01);
            aA23 = ffma2(pa, sA23, aA23);
            aB01 = ffma2(pb, sB01, aB01);
            aB23 = ffma2(pb, sB23, aB23);
        }
    }

    float f0, f1, f2, f3;
    if (va) {
        unpack2(aA01, f0, f1);
        unpack2(aA23, f2, f3);
        out[ta] = make_float4(f0, f1, f2, f3);
    }
    if (vb) {
        unpack2(aB01, f0, f1);
        unpack2(aB23, f2, f3);
        out[tb] = make_float4(f0, f1, f2, f3);
    }
}

// ---------------------------------------------------------------------------
extern "C" void kernel_launch(void* const* d_in, const int* in_sizes, int n_in,
                              void* d_out, int out_size) {
    const float* patches = (const float*)d_in[0];
    int B = in_sizes[0] / 4;

    build_coef_kernel<<<1, 384>>>(
        (const float*)d_in[1], (const float*)d_in[2], (const float*)d_in[3],
        (const float*)d_in[4], (const float*)d_in[5], (const float*)d_in[6],
        (const float*)d_in[7], (const float*)d_in[8], (const float*)d_in[9],
        (const float*)d_in[10], (const float*)d_in[11], (const float*)d_in[12],
        (const float*)d_in[13], (const float*)d_in[14]);

    // PDL launch: main kernel may start early; it grid-depsyncs before
    // reading g_coef.
    cudaLaunchConfig_t cfg = {};
    cfg.gridDim = dim3((unsigned)((B + 511) / 512));
    cfg.blockDim = dim3(256);
    cfg.dynamicSmemBytes = 0;
    cfg.stream = 0;
    cudaLaunchAttribute attr[1];
    attr[0].id = cudaLaunchAttributeProgrammaticStreamSerialization;
    attr[0].val.programmaticStreamSerializationAllowed = 1;
    cfg.attrs = attr;
    cfg.numAttrs = 1;
    cudaLaunchKernelEx(&cfg, quanv_main, (const float4*)patches, (float4*)d_out, B);
}